// round 5
// baseline (speedup 1.0000x reference)
#include <cuda_runtime.h>

// ============================================================================
// EDF ensemble detection fusion, N = 8192.
// Pipeline:
//   K0  init scratch + build 64-bit sort keys (score desc, idx asc)
//   K1b rank-by-counting (stable argsort)            ~8 us
//   K1c gather sorted boxes, clip, precompute areas
//   K2  upper-triangle IoU -> edge list + in-degree  ~25 us (dominant)
//   K3  prefix scan of in-degrees -> CSR offsets
//   K4  scatter edges into in-neighbor CSR
//   K5  parallel fixpoint for lexicographic-first-MIS greedy clustering
//   K7  per-cluster stats (count, sum s, max y2) via atomics
//   K8  first index achieving the cluster max-y2
//   K9  final keep/output
// ============================================================================

#define NN 8192
#define ECAP (1 << 18)
#define W_IMG 1920.0f
#define H_IMG 1080.0f

__device__ unsigned long long g_keys[NN];
__device__ int   g_rank[NN];
__device__ float g_bx1[NN], g_by1[NN], g_bx2[NN], g_by2[NN], g_s[NN], g_area[NN];
__device__ int   g_degIn[NN];
__device__ int   g_inOff[NN + 1];
__device__ int   g_cursor[NN];
__device__ int   g_eh[ECAP], g_ej[ECAP], g_inList[ECAP];
__device__ int   g_ecnt;
__device__ int   g_cluster[NN];
__device__ int   g_count[NN];
__device__ float g_sum[NN];
__device__ unsigned g_maxY2[NN];
__device__ int   g_first[NN];

// ---------------------------------------------------------------------------
// K0: zero scratch, build sort keys. Key = (~score_bits << 32) | idx.
// Scores are positive so raw fp32 bits are order-preserving; ~bits makes the
// ascending-key order = descending score; low 32 bits = original index gives
// the stable tiebreak (matches jnp stable argsort of -scores).
// ---------------------------------------------------------------------------
__global__ void k_init(const float* __restrict__ scores) {
    int i = blockIdx.x * blockDim.x + threadIdx.x;
    if (i < NN) {
        unsigned fb = __float_as_uint(scores[i]);
        g_keys[i] = (((unsigned long long)(~fb)) << 32) | (unsigned)i;
        g_rank[i]   = 0;
        g_degIn[i]  = 0;
        g_cursor[i] = 0;
        g_count[i]  = 0;
        g_sum[i]    = 0.0f;
        g_maxY2[i]  = 0u;            // by2 >= 0, so 0-bits is a valid -inf
        g_first[i]  = NN;
    }
    if (i == 0) g_ecnt = 0;
}

// ---------------------------------------------------------------------------
// K1b: rank by counting. Block (bx, by): rows bx*256.., key-chunk by*2048..
// Shared-tiled keys are broadcast-read (all lanes same address) -> ~4 instr
// per 32 comparisons per warp.
// ---------------------------------------------------------------------------
__global__ void k_rank() {
    __shared__ unsigned long long sk[2048];
    int i = blockIdx.x * 256 + threadIdx.x;
    int kbase = blockIdx.y * 2048;
    for (int t = threadIdx.x; t < 2048; t += 256) sk[t] = g_keys[kbase + t];
    __syncthreads();
    unsigned long long my = g_keys[i];
    int c = 0;
#pragma unroll 8
    for (int t = 0; t < 2048; t++) c += (sk[t] < my) ? 1 : 0;
    atomicAdd(&g_rank[i], c);
}

// ---------------------------------------------------------------------------
// K1c: scatter into sorted position; clip boxes; precompute +1 areas.
// Deliberate __f*_rn intrinsics: no FMA contraction, no fast-math div later.
// ---------------------------------------------------------------------------
__global__ void k_gather(const float* __restrict__ boxes,
                         const float* __restrict__ scores) {
    int i = blockIdx.x * blockDim.x + threadIdx.x;
    if (i >= NN) return;
    int p = g_rank[i];
    float x1 = boxes[i * 4 + 0];
    float y1 = boxes[i * 4 + 1];
    float x2 = boxes[i * 4 + 2];
    float y2 = boxes[i * 4 + 3];
    x1 = fminf(fmaxf(x1, 0.0f), W_IMG);
    y1 = fminf(fmaxf(y1, 0.0f), H_IMG);
    x2 = fminf(fmaxf(x2, 0.0f), W_IMG);
    y2 = fminf(fmaxf(y2, 0.0f), H_IMG);
    g_bx1[p] = x1; g_by1[p] = y1; g_bx2[p] = x2; g_by2[p] = y2;
    g_s[p] = scores[i];
    float aw = __fadd_rn(__fsub_rn(x2, x1), 1.0f);
    float ah = __fadd_rn(__fsub_rn(y2, y1), 1.0f);
    g_area[p] = __fmul_rn(aw, ah);
}

// ---------------------------------------------------------------------------
// K2: warp-per-row IoU over j > i. Appends edges (i<j) and counts in-degree.
// Division only when inter > 0 (~2% of pairs). __fdiv_rn for exact rounding
// at the 0.5 threshold.
// ---------------------------------------------------------------------------
__global__ void k_edges() {
    int warp = (blockIdx.x * blockDim.x + threadIdx.x) >> 5;
    int lane = threadIdx.x & 31;
    if (warp >= NN) return;
    int i = warp;
    float ax1 = g_bx1[i], ay1 = g_by1[i], ax2 = g_bx2[i], ay2 = g_by2[i];
    float aa  = g_area[i];
    for (int w = i >> 5; w < NN / 32; w++) {
        int j = (w << 5) | lane;
        bool adj = false;
        if (j > i) {
            float ix1 = fmaxf(ax1, g_bx1[j]);
            float iy1 = fmaxf(ay1, g_by1[j]);
            float ix2 = fminf(ax2, g_bx2[j]);
            float iy2 = fminf(ay2, g_by2[j]);
            float iw = fmaxf(__fadd_rn(__fsub_rn(ix2, ix1), 1.0f), 0.0f);
            float ih = fmaxf(__fadd_rn(__fsub_rn(iy2, iy1), 1.0f), 0.0f);
            float inter = __fmul_rn(iw, ih);
            if (inter > 0.0f) {
                float uni = __fsub_rn(__fadd_rn(aa, g_area[j]), inter);
                adj = __fdiv_rn(inter, uni) > 0.5f;
            }
        }
        if (adj) {
            int e = atomicAdd(&g_ecnt, 1);
            if (e < ECAP) {
                g_eh[e] = i;
                g_ej[e] = j;
                atomicAdd(&g_degIn[j], 1);
            }
        }
    }
}

// ---------------------------------------------------------------------------
// K3: single-block exclusive scan of g_degIn -> g_inOff (8193 entries).
// ---------------------------------------------------------------------------
__global__ void k_scan() {
    __shared__ int s_sums[1024];
    int tid = threadIdx.x;
    int base = tid * 8;
    int v[8], ex[8];
    int sum = 0;
#pragma unroll
    for (int r = 0; r < 8; r++) {
        v[r] = g_degIn[base + r];
        ex[r] = sum;
        sum += v[r];
    }
    s_sums[tid] = sum;
    __syncthreads();
    for (int off = 1; off < 1024; off <<= 1) {
        int t = (tid >= off) ? s_sums[tid - off] : 0;
        __syncthreads();
        s_sums[tid] += t;
        __syncthreads();
    }
    int blockEx = s_sums[tid] - sum;
#pragma unroll
    for (int r = 0; r < 8; r++) g_inOff[base + r] = blockEx + ex[r];
    if (tid == 1023) g_inOff[NN] = blockEx + sum;
}

// ---------------------------------------------------------------------------
// K4: scatter edges into in-neighbor CSR (order within a list is irrelevant:
// the fixpoint only takes mins / all-of checks).
// ---------------------------------------------------------------------------
__global__ void k_fill() {
    int e = blockIdx.x * blockDim.x + threadIdx.x;
    int ec = g_ecnt;
    if (ec > ECAP) ec = ECAP;
    if (e >= ec) return;
    int j = g_ej[e];
    int pos = g_inOff[j] + atomicAdd(&g_cursor[j], 1);
    g_inList[pos] = g_eh[e];
}

// ---------------------------------------------------------------------------
// K5: parallel fixpoint for the greedy scan (lexicographic-first MIS).
// State per node in shared: -1 undecided, ==i head, in [0,i) nonhead.
// A node decides:
//   head          if all earlier neighbors are decided nonhead
//   cluster = m   if min decided-head m < min undecided earlier neighbor
// The minimum undecided index always resolves each round -> termination.
// ---------------------------------------------------------------------------
__global__ void k_cluster() {
    __shared__ int sc[NN];
    __shared__ int s_ch;
    int tid = threadIdx.x;
    for (int i = tid; i < NN; i += 1024) sc[i] = -1;
    __syncthreads();

    for (int round = 0; round < 256; round++) {
        if (tid == 0) s_ch = 0;
        __syncthreads();
        for (int i = tid; i < NN; i += 1024) {
            if (sc[i] < 0) {
                int b = g_inOff[i], e = g_inOff[i + 1];
                int m = 0x7fffffff, u = 0x7fffffff;
                for (int p = b; p < e; p++) {
                    int h = g_inList[p];
                    int c = sc[h];
                    if (c == h)      m = min(m, h);
                    else if (c < 0)  u = min(u, h);
                }
                if (m < u)                 { sc[i] = m; s_ch = 1; }
                else if (u == 0x7fffffff)  { sc[i] = i; s_ch = 1; } // m==INF too
            }
        }
        __syncthreads();
        int done = (s_ch == 0);
        __syncthreads();
        if (done) break;
    }
    for (int i = tid; i < NN; i += 1024) g_cluster[i] = sc[i];
}

// ---------------------------------------------------------------------------
// K7: per-cluster stats.
// ---------------------------------------------------------------------------
__global__ void k_stats() {
    int j = blockIdx.x * blockDim.x + threadIdx.x;
    if (j >= NN) return;
    int c = g_cluster[j];
    atomicAdd(&g_count[c], 1);
    atomicAdd(&g_sum[c], g_s[j]);
    atomicMax(&g_maxY2[c], __float_as_uint(g_by2[j])); // by2 >= 0: bits monotone
}

// ---------------------------------------------------------------------------
// K8: first (smallest sorted index) member achieving the cluster's max y2.
// ---------------------------------------------------------------------------
__global__ void k_first() {
    int j = blockIdx.x * blockDim.x + threadIdx.x;
    if (j >= NN) return;
    int c = g_cluster[j];
    if (g_by2[j] >= __uint_as_float(g_maxY2[c])) atomicMin(&g_first[c], j);
}

// ---------------------------------------------------------------------------
// K9: keep + output. Layout: out[0 .. 5N) = (N,5) fused rows, out[5N .. 6N) =
// keep as 0/1 floats (harness flattens the (out, keep) tuple to fp32).
// valid: counts >= nm/3.0  <=>  3*count >= nm (exact for integer counts).
// ---------------------------------------------------------------------------
__global__ void k_out(const int* __restrict__ nmp, float* __restrict__ out,
                      int out_size) {
    int j = blockIdx.x * blockDim.x + threadIdx.x;
    if (j >= NN) return;
    int nm = nmp[0];
    if (nm < 1 || nm > 1000000) {
        // defensive: num_models may arrive as a float-encoded scalar
        float f = __int_as_float(nm);
        nm = (int)f;
        if (nm < 1) nm = 1;
    }
    int c = g_cluster[j];
    bool keep = (j == g_first[c]) && (3 * g_count[c] >= nm);
    float r0 = 0.f, r1 = 0.f, r2 = 0.f, r3 = 0.f, r4 = 0.f, kf = 0.f;
    if (keep) {
        r0 = g_bx1[j]; r1 = g_by1[j]; r2 = g_bx2[j]; r3 = g_by2[j];
        r4 = __fdiv_rn(g_sum[c], (float)nm);
        kf = 1.0f;
    }
    long long base = (long long)j * 5;
    if (base + 4 < out_size) {
        out[base + 0] = r0; out[base + 1] = r1; out[base + 2] = r2;
        out[base + 3] = r3; out[base + 4] = r4;
    }
    long long kpos = (long long)NN * 5 + j;
    if (kpos < out_size) out[kpos] = kf;
}

// ---------------------------------------------------------------------------
extern "C" void kernel_launch(void* const* d_in, const int* in_sizes, int n_in,
                              void* d_out, int out_size) {
    // Identify inputs by element count (boxes = 4N, scores = N, num_models = 1)
    const float* boxes  = nullptr;
    const float* scores = nullptr;
    const int*   nmp    = nullptr;
    for (int k = 0; k < n_in; k++) {
        if (in_sizes[k] == NN * 4)      boxes  = (const float*)d_in[k];
        else if (in_sizes[k] == NN)     scores = (const float*)d_in[k];
        else if (in_sizes[k] == 1)      nmp    = (const int*)d_in[k];
    }
    if (!boxes)  boxes  = (const float*)d_in[0];
    if (!scores) scores = (const float*)d_in[1];
    if (!nmp)    nmp    = (const int*)d_in[n_in - 1];

    float* out = (float*)d_out;

    k_init<<<NN / 256, 256>>>(scores);
    k_rank<<<dim3(NN / 256, 4), 256>>>();
    k_gather<<<NN / 256, 256>>>(boxes, scores);
    k_edges<<<NN / 8, 256>>>();          // 8 warps/block, warp-per-row
    k_scan<<<1, 1024>>>();
    k_fill<<<ECAP / 256, 256>>>();
    k_cluster<<<1, 1024>>>();
    k_stats<<<NN / 256, 256>>>();
    k_first<<<NN / 256, 256>>>();
    k_out<<<NN / 256, 256>>>(nmp, out, out_size);
}

// round 7
// speedup vs baseline: 1.0746x; 1.0746x over previous
#include <cuda_runtime.h>

// ============================================================================
// EDF ensemble detection fusion, N = 8192.  R6: x-sorted spatial pruning of
// the IoU pair space (33.5M -> ~3.5M pairs), fused rank sorts, fused tail.
//
// Launches:
//   K0 k_init   : zero scratch, build score keys + x1 keys
//   K1 k_rank2  : counting-rank for BOTH key sets (blockIdx.z selects)
//   K2 k_gather : clip, scatter to score-sorted SoA + x-sorted float4 SoA
//   K3 k_edges  : warp-per-x-row, break-early candidate scan, exact IoU
//   K4 k_post   : single block: CSR scan+fill, greedy-cluster fixpoint,
//                 segment stats, first-pick, output
// ============================================================================

#define NN 8192
#define ECAP (1 << 18)
#define W_IMG 1920.0f
#define H_IMG 1080.0f

__device__ unsigned long long g_keys[NN];    // score-desc keys
__device__ unsigned long long g_xkeys[NN];   // x1-asc keys
__device__ int   g_rank[NN];                 // score rank of original i
__device__ int   g_xrank[NN];                // x rank of original i
__device__ float g_bx1[NN], g_by1[NN], g_bx2[NN], g_by2[NN], g_s[NN], g_area[NN];
__device__ float4 g_xs4[NN];                 // x-sorted clipped boxes
__device__ float  g_xarea[NN];               // x-sorted areas
__device__ int    g_xord[NN];                // x-rank -> score-rank
__device__ int   g_degIn[NN];
__device__ int   g_inOff[NN + 1];
__device__ int   g_cursor[NN];
__device__ int   g_eh[ECAP], g_ej[ECAP], g_inList[ECAP];
__device__ int   g_ecnt;
__device__ int   g_count[NN];
__device__ float g_sum[NN];
__device__ unsigned g_maxY2[NN];
__device__ int   g_first[NN];

// ---------------------------------------------------------------------------
// K0: zero scratch; build both key sets.
//  score key = (~bits(score) << 32) | i   -> ascending = score desc, stable
//  x key     = ( bits(clip(x1)) << 32) | i -> ascending = x1 asc
// (scores and clipped x1 are >= 0, so raw fp32 bits are order-preserving)
// ---------------------------------------------------------------------------
__global__ void k_init(const float* __restrict__ scores,
                       const float* __restrict__ boxes) {
    int i = blockIdx.x * blockDim.x + threadIdx.x;
    if (i < NN) {
        unsigned fb = __float_as_uint(scores[i]);
        g_keys[i] = (((unsigned long long)(~fb)) << 32) | (unsigned)i;
        float x1 = fminf(fmaxf(boxes[i * 4 + 0], 0.0f), W_IMG);
        g_xkeys[i] = (((unsigned long long)__float_as_uint(x1)) << 32) | (unsigned)i;
        g_rank[i]   = 0;
        g_xrank[i]  = 0;
        g_degIn[i]  = 0;
        g_cursor[i] = 0;
        g_count[i]  = 0;
        g_sum[i]    = 0.0f;
        g_maxY2[i]  = 0u;            // y2 >= 0 -> 0-bits is a valid -inf
        g_first[i]  = NN;
    }
    if (i == 0) g_ecnt = 0;
}

// ---------------------------------------------------------------------------
// K1: rank-by-counting for both key arrays. blockIdx.z: 0=score, 1=x.
// Shared-tiled keys, broadcast reads.
// ---------------------------------------------------------------------------
__global__ void k_rank2() {
    __shared__ unsigned long long sk[2048];
    const unsigned long long* __restrict__ keys = blockIdx.z ? g_xkeys : g_keys;
    int* __restrict__ rank = blockIdx.z ? g_xrank : g_rank;
    int i = blockIdx.x * 256 + threadIdx.x;
    int kbase = blockIdx.y * 2048;
    for (int t = threadIdx.x; t < 2048; t += 256) sk[t] = keys[kbase + t];
    __syncthreads();
    unsigned long long my = keys[i];
    int c = 0;
#pragma unroll 8
    for (int t = 0; t < 2048; t++) c += (sk[t] < my) ? 1 : 0;
    atomicAdd(&rank[i], c);
}

// ---------------------------------------------------------------------------
// K2: clip boxes, scatter into score-sorted SoA (position p) AND x-sorted
// packed SoA (position r). __f*_rn keeps ref-exact arithmetic (no contraction).
// ---------------------------------------------------------------------------
__global__ void k_gather(const float* __restrict__ boxes,
                         const float* __restrict__ scores) {
    int i = blockIdx.x * blockDim.x + threadIdx.x;
    if (i >= NN) return;
    int p = g_rank[i];
    int r = g_xrank[i];
    float x1 = fminf(fmaxf(boxes[i * 4 + 0], 0.0f), W_IMG);
    float y1 = fminf(fmaxf(boxes[i * 4 + 1], 0.0f), H_IMG);
    float x2 = fminf(fmaxf(boxes[i * 4 + 2], 0.0f), W_IMG);
    float y2 = fminf(fmaxf(boxes[i * 4 + 3], 0.0f), H_IMG);
    g_bx1[p] = x1; g_by1[p] = y1; g_bx2[p] = x2; g_by2[p] = y2;
    g_s[p] = scores[i];
    float aw = __fadd_rn(__fsub_rn(x2, x1), 1.0f);
    float ah = __fadd_rn(__fsub_rn(y2, y1), 1.0f);
    float area = __fmul_rn(aw, ah);
    g_area[p] = area;
    g_xs4[r] = make_float4(x1, y1, x2, y2);
    g_xarea[r] = area;
    g_xord[r] = p;
}

// ---------------------------------------------------------------------------
// K3: warp per x-sorted row a. Candidates b > a are a contiguous run while
// x1_b <= x2_a + 2 (conservative: iw>0 implies x1_b < min(x2)+1+ulp, so +2
// is a strict superset -> identical edge set, decided by exact ref math).
// Edges recorded in score-index space (i<j), with in-degree counting.
// ---------------------------------------------------------------------------
__global__ void k_edges() {
    int warp = (blockIdx.x * blockDim.x + threadIdx.x) >> 5;
    int lane = threadIdx.x & 31;
    if (warp >= NN) return;
    int a = warp;
    float4 A = g_xs4[a];
    float aa = g_xarea[a];
    int   pa = g_xord[a];
    float thresh = A.z + 2.0f;

    for (int b0 = a + 1; b0 < NN; b0 += 32) {
        int b = b0 + lane;
        bool in = b < NN;
        float4 B = in ? g_xs4[b] : make_float4(3.0e30f, 0.f, 0.f, 0.f);
        bool scr = B.x <= thresh;
        if (in && scr) {
            // exact reference arithmetic
            float ix1 = fmaxf(A.x, B.x);
            float iy1 = fmaxf(A.y, B.y);
            float ix2 = fminf(A.z, B.z);
            float iy2 = fminf(A.w, B.w);
            float iw = fmaxf(__fadd_rn(__fsub_rn(ix2, ix1), 1.0f), 0.0f);
            float ih = fmaxf(__fadd_rn(__fsub_rn(iy2, iy1), 1.0f), 0.0f);
            float inter = __fmul_rn(iw, ih);
            if (inter > 0.0f) {
                float uni = __fsub_rn(__fadd_rn(aa, g_xarea[b]), inter);
                if (__fdiv_rn(inter, uni) > 0.5f) {
                    int pb = g_xord[b];
                    int i = min(pa, pb);
                    int j = max(pa, pb);
                    int e = atomicAdd(&g_ecnt, 1);
                    if (e < ECAP) {
                        g_eh[e] = i;
                        g_ej[e] = j;
                        atomicAdd(&g_degIn[j], 1);
                    }
                }
            }
        }
        if (__any_sync(0xffffffffu, !scr)) break;   // sorted -> no more cands
    }
}

// ---------------------------------------------------------------------------
// K4: fused single-block tail.
//  (a) exclusive scan of in-degrees -> CSR offsets
//  (b) scatter edges into in-neighbor CSR
//  (c) parallel fixpoint for the greedy scan (lexicographic-first MIS):
//      node decides head iff all earlier neighbors decided nonhead; decides
//      cluster=m (min decided head) iff m < min undecided earlier neighbor.
//  (d) segment stats (count / sum-score / max-y2) via atomics
//  (e) first index achieving the segment max-y2
//  (f) keep + output
// ---------------------------------------------------------------------------
__global__ void k_post(const int* __restrict__ nmp, float* __restrict__ out,
                       int out_size) {
    __shared__ int sc[NN];
    __shared__ int s_sums[1024];
    __shared__ int s_ch;
    int tid = threadIdx.x;

    // (a) scan
    {
        int base = tid * 8;
        int ex[8];
        int sum = 0;
#pragma unroll
        for (int r = 0; r < 8; r++) {
            int v = g_degIn[base + r];
            ex[r] = sum;
            sum += v;
        }
        s_sums[tid] = sum;
        __syncthreads();
        for (int off = 1; off < 1024; off <<= 1) {
            int t = (tid >= off) ? s_sums[tid - off] : 0;
            __syncthreads();
            s_sums[tid] += t;
            __syncthreads();
        }
        int blockEx = s_sums[tid] - sum;
#pragma unroll
        for (int r = 0; r < 8; r++) g_inOff[base + r] = blockEx + ex[r];
        if (tid == 1023) g_inOff[NN] = blockEx + sum;
    }
    __syncthreads();

    // (b) CSR fill
    {
        int ec = g_ecnt;
        if (ec > ECAP) ec = ECAP;
        for (int e = tid; e < ec; e += 1024) {
            int j = g_ej[e];
            int pos = g_inOff[j] + atomicAdd(&g_cursor[j], 1);
            g_inList[pos] = g_eh[e];
        }
    }
    for (int i = tid; i < NN; i += 1024) sc[i] = -1;
    __syncthreads();

    // (c) fixpoint
    for (int round = 0; round < 256; round++) {
        if (tid == 0) s_ch = 0;
        __syncthreads();
        for (int i = tid; i < NN; i += 1024) {
            if (sc[i] < 0) {
                int b = g_inOff[i], e = g_inOff[i + 1];
                int m = 0x7fffffff, u = 0x7fffffff;
                for (int p = b; p < e; p++) {
                    int h = g_inList[p];
                    int c = sc[h];
                    if (c == h)      m = min(m, h);
                    else if (c < 0)  u = min(u, h);
                }
                if (m < u)                 { sc[i] = m; s_ch = 1; }
                else if (u == 0x7fffffff)  { sc[i] = i; s_ch = 1; }
            }
        }
        __syncthreads();
        int done = (s_ch == 0);
        __syncthreads();
        if (done) break;
    }

    // (d) stats
    for (int j = tid; j < NN; j += 1024) {
        int c = sc[j];
        atomicAdd(&g_count[c], 1);
        atomicAdd(&g_sum[c], g_s[j]);
        atomicMax(&g_maxY2[c], __float_as_uint(g_by2[j]));  // y2>=0: bits monotone
    }
    __syncthreads();

    // (e) first pick
    for (int j = tid; j < NN; j += 1024) {
        int c = sc[j];
        if (g_by2[j] >= __uint_as_float(g_maxY2[c])) atomicMin(&g_first[c], j);
    }
    __syncthreads();

    // (f) output: out[0..5N) = (N,5) rows, out[5N..6N) = keep as 0/1 floats.
    //     valid: counts >= nm/3  <=>  3*count >= nm (exact in ints)
    int nm = nmp[0];
    if (nm < 1 || nm > 1000000) {
        float f = __int_as_float(nm);
        nm = (int)f;
        if (nm < 1) nm = 1;
    }
    for (int j = tid; j < NN; j += 1024) {
        int c = sc[j];
        bool keep = (j == g_first[c]) && (3 * g_count[c] >= nm);
        float r0 = 0.f, r1 = 0.f, r2 = 0.f, r3 = 0.f, r4 = 0.f, kf = 0.f;
        if (keep) {
            r0 = g_bx1[j]; r1 = g_by1[j]; r2 = g_bx2[j]; r3 = g_by2[j];
            r4 = __fdiv_rn(g_sum[c], (float)nm);
            kf = 1.0f;
        }
        long long base = (long long)j * 5;
        if (base + 4 < out_size) {
            out[base + 0] = r0; out[base + 1] = r1; out[base + 2] = r2;
            out[base + 3] = r3; out[base + 4] = r4;
        }
        long long kpos = (long long)NN * 5 + j;
        if (kpos < out_size) out[kpos] = kf;
    }
}

// ---------------------------------------------------------------------------
extern "C" void kernel_launch(void* const* d_in, const int* in_sizes, int n_in,
                              void* d_out, int out_size) {
    const float* boxes  = nullptr;
    const float* scores = nullptr;
    const int*   nmp    = nullptr;
    for (int k = 0; k < n_in; k++) {
        if (in_sizes[k] == NN * 4)      boxes  = (const float*)d_in[k];
        else if (in_sizes[k] == NN)     scores = (const float*)d_in[k];
        else if (in_sizes[k] == 1)      nmp    = (const int*)d_in[k];
    }
    if (!boxes)  boxes  = (const float*)d_in[0];
    if (!scores) scores = (const float*)d_in[1];
    if (!nmp)    nmp    = (const int*)d_in[n_in - 1];

    float* out = (float*)d_out;

    k_init<<<NN / 256, 256>>>(scores, boxes);
    k_rank2<<<dim3(NN / 256, 4, 2), 256>>>();
    k_gather<<<NN / 256, 256>>>(boxes, scores);
    k_edges<<<NN / 8, 256>>>();            // 8192 warps, warp per x-row
    k_post<<<1, 1024>>>(nmp, out, out_size);
}

// round 8
// speedup vs baseline: 1.3647x; 1.2699x over previous
#include <cuda_runtime.h>

// ============================================================================
// EDF ensemble detection fusion, N = 8192.  R7:
//  - x-order via 256-bin bucket sort (no second counting sort)
//  - k_edges: range known upfront, area_b recomputed (1 LDG.128/candidate)
//  - k_post: shared u16 CSR offsets + i16 cluster state + worklist fixpoint
//
// Launches:
//   K0 k_init   : zero scratch, score keys, x-bins
//   K1 k_rank   : counting-rank for score keys; spare block scans bin hist
//   K2 k_gather : clip, scatter to score-sorted SoA + bin-sorted float4 SoA
//   K3 k_edges  : warp-per-x-row exact IoU over pruned candidate range
//   K4 k_post   : CSR + greedy-cluster worklist fixpoint + stats + output
// ============================================================================

#define NN 8192
#define ECAP 60000
#define BINS 256
#define INV_BINW (256.0f / 1920.0f)
#define W_IMG 1920.0f
#define H_IMG 1080.0f

__device__ unsigned long long g_keys[NN];    // score-desc keys
__device__ int    g_rank[NN];                // score rank of original i
__device__ int    g_bin[NN];                 // x bin of original i
__device__ int    g_binOff[BINS + 1];
__device__ int    g_binCur[BINS];
__device__ float  g_bx1[NN], g_by1[NN], g_bx2[NN], g_by2[NN], g_s[NN];
__device__ float4 g_xs4[NN];                 // bin-sorted clipped boxes
__device__ int    g_xord[NN];                // bin-pos -> score-rank
__device__ int    g_degIn[NN];
__device__ int    g_cursor[NN];
__device__ int    g_eh[ECAP], g_ej[ECAP], g_inList[ECAP];
__device__ int    g_ecnt;
__device__ int    g_actA[NN], g_actB[NN];
__device__ int    g_count[NN];
__device__ float  g_sum[NN];
__device__ unsigned g_maxY2[NN];
__device__ int    g_first[NN];

// ---------------------------------------------------------------------------
// K0: zero scratch; score keys = (~bits(score) << 32) | i  (stable desc);
// x bin from clipped x1 (monotone bucketing).
// ---------------------------------------------------------------------------
__global__ void k_init(const float* __restrict__ scores,
                       const float* __restrict__ boxes) {
    int i = blockIdx.x * blockDim.x + threadIdx.x;
    if (i < NN) {
        unsigned fb = __float_as_uint(scores[i]);
        g_keys[i] = (((unsigned long long)(~fb)) << 32) | (unsigned)i;
        float x1 = fminf(fmaxf(boxes[i * 4 + 0], 0.0f), W_IMG);
        int b = (int)(x1 * INV_BINW);
        if (b > BINS - 1) b = BINS - 1;
        g_bin[i]    = b;
        g_rank[i]   = 0;
        g_degIn[i]  = 0;
        g_cursor[i] = 0;
        g_count[i]  = 0;
        g_sum[i]    = 0.0f;
        g_maxY2[i]  = 0u;            // y2 >= 0 -> 0-bits is a valid -inf
        g_first[i]  = NN;
    }
    if (i < BINS) g_binCur[i] = 0;
    if (i == 0) g_ecnt = 0;
}

// ---------------------------------------------------------------------------
// K1: counting-rank on score keys (blocks x<32). Block x==32,y==0 builds the
// 256-bin histogram + exclusive scan -> g_binOff.
// ---------------------------------------------------------------------------
__global__ void k_rank() {
    if (blockIdx.x == 32) {
        if (blockIdx.y != 0) return;
        __shared__ int hist[BINS];
        int tid = threadIdx.x;
        hist[tid] = 0;
        __syncthreads();
        for (int i = tid; i < NN; i += 256) atomicAdd(&hist[g_bin[i]], 1);
        __syncthreads();
        int val = hist[tid];
        for (int off = 1; off < BINS; off <<= 1) {
            int t = (tid >= off) ? hist[tid - off] : 0;
            __syncthreads();
            hist[tid] += t;
            __syncthreads();
        }
        g_binOff[tid] = hist[tid] - val;           // exclusive
        if (tid == BINS - 1) g_binOff[BINS] = hist[BINS - 1];
        return;
    }
    __shared__ unsigned long long sk[2048];
    int i = blockIdx.x * 256 + threadIdx.x;
    int kbase = blockIdx.y * 2048;
    for (int t = threadIdx.x; t < 2048; t += 256) sk[t] = g_keys[kbase + t];
    __syncthreads();
    unsigned long long my = g_keys[i];
    int c = 0;
#pragma unroll 8
    for (int t = 0; t < 2048; t++) c += (sk[t] < my) ? 1 : 0;
    atomicAdd(&g_rank[i], c);
}

// ---------------------------------------------------------------------------
// K2: clip, scatter to score-sorted SoA (pos p) and bin-sorted float4 (pos r).
// In-bucket order is arbitrary: edge set + all downstream results invariant.
// ---------------------------------------------------------------------------
__global__ void k_gather(const float* __restrict__ boxes,
                         const float* __restrict__ scores) {
    int i = blockIdx.x * blockDim.x + threadIdx.x;
    if (i >= NN) return;
    int p = g_rank[i];
    float x1 = fminf(fmaxf(boxes[i * 4 + 0], 0.0f), W_IMG);
    float y1 = fminf(fmaxf(boxes[i * 4 + 1], 0.0f), H_IMG);
    float x2 = fminf(fmaxf(boxes[i * 4 + 2], 0.0f), W_IMG);
    float y2 = fminf(fmaxf(boxes[i * 4 + 3], 0.0f), H_IMG);
    g_bx1[p] = x1; g_by1[p] = y1; g_bx2[p] = x2; g_by2[p] = y2;
    g_s[p] = scores[i];
    int b = g_bin[i];
    int r = g_binOff[b] + atomicAdd(&g_binCur[b], 1);
    g_xs4[r] = make_float4(x1, y1, x2, y2);
    g_xord[r] = p;
}

// ---------------------------------------------------------------------------
// K3: warp per bin-sorted row a. Candidates: positions (a, end) where
// end = binOff[bin(x2_a + 2) + 1]. Any intersecting pair with pos_b > pos_a
// satisfies x1_b <= x2_a + 1 < x2_a + 2 -> inside range (conservative).
// Exact reference arithmetic decides; area_b recomputed (identical formula
// to reference -> bit-identical to a stored value).
// ---------------------------------------------------------------------------
__global__ void k_edges() {
    int warp = (blockIdx.x * blockDim.x + threadIdx.x) >> 5;
    int lane = threadIdx.x & 31;
    if (warp >= NN) return;
    int a = warp;
    float4 A = g_xs4[a];
    int   pa = g_xord[a];
    float aa = __fmul_rn(__fadd_rn(__fsub_rn(A.z, A.x), 1.0f),
                         __fadd_rn(__fsub_rn(A.w, A.y), 1.0f));
    float thresh = A.z + 2.0f;
    int binMax = (int)(thresh * INV_BINW);
    if (binMax > BINS - 1) binMax = BINS - 1;
    int end = g_binOff[binMax + 1];

    for (int b0 = a + 1; b0 < end; b0 += 32) {
        int b = b0 + lane;
        if (b < end) {
            float4 B = g_xs4[b];
            if (B.x <= thresh) {
                float ix1 = fmaxf(A.x, B.x);
                float iy1 = fmaxf(A.y, B.y);
                float ix2 = fminf(A.z, B.z);
                float iy2 = fminf(A.w, B.w);
                float iw = fmaxf(__fadd_rn(__fsub_rn(ix2, ix1), 1.0f), 0.0f);
                float ih = fmaxf(__fadd_rn(__fsub_rn(iy2, iy1), 1.0f), 0.0f);
                float inter = __fmul_rn(iw, ih);
                if (inter > 0.0f) {
                    float ab = __fmul_rn(__fadd_rn(__fsub_rn(B.z, B.x), 1.0f),
                                         __fadd_rn(__fsub_rn(B.w, B.y), 1.0f));
                    float uni = __fsub_rn(__fadd_rn(aa, ab), inter);
                    if (__fdiv_rn(inter, uni) > 0.5f) {
                        int pb = g_xord[b];
                        int i = min(pa, pb);
                        int j = max(pa, pb);
                        int e = atomicAdd(&g_ecnt, 1);
                        if (e < ECAP) {
                            g_eh[e] = i;
                            g_ej[e] = j;
                            atomicAdd(&g_degIn[j], 1);
                        }
                    }
                }
            }
        }
    }
}

// ---------------------------------------------------------------------------
// K4: fused single-block tail.
//  (a) exclusive scan of in-degrees -> shared u16 CSR offsets
//  (b) scatter edges into in-neighbor CSR
//  (c) worklist fixpoint for the greedy scan (lexicographic-first MIS):
//      deg-0 nodes decide head at init; rounds process only undecided nodes.
//      decide head iff all earlier nbrs decided nonhead; decide cluster=m
//      (min decided head) iff m < min undecided earlier nbr.
//  (d) segment stats, (e) first-pick, (f) keep + output
// ---------------------------------------------------------------------------
__global__ void k_post(const int* __restrict__ nmp, float* __restrict__ out,
                       int out_size) {
    __shared__ short          s_sc[NN];      // -1 undecided / cluster id
    __shared__ unsigned short s_off[NN];     // CSR starts (total < 65536)
    __shared__ int            s_sums[1024];
    __shared__ int            s_total, s_cnt;
    int tid = threadIdx.x;

    // (a) scan of g_degIn -> s_off (exclusive), s_total
    int base = tid * 8;
    int ex[8];
    int sum = 0;
#pragma unroll
    for (int r = 0; r < 8; r++) {
        int v = g_degIn[base + r];
        ex[r] = sum;
        sum += v;
    }
    s_sums[tid] = sum;
    __syncthreads();
    for (int off = 1; off < 1024; off <<= 1) {
        int t = (tid >= off) ? s_sums[tid - off] : 0;
        __syncthreads();
        s_sums[tid] += t;
        __syncthreads();
    }
    int blockEx = s_sums[tid] - sum;
#pragma unroll
    for (int r = 0; r < 8; r++)
        s_off[base + r] = (unsigned short)(blockEx + ex[r]);
    if (tid == 1023) s_total = blockEx + sum;
    if (tid == 0) s_cnt = 0;
    __syncthreads();
    int total = s_total;

    // (b) CSR fill
    {
        int ec = g_ecnt;
        if (ec > ECAP) ec = ECAP;
        for (int e = tid; e < ec; e += 1024) {
            int j = g_ej[e];
            int pos = (int)s_off[j] + atomicAdd(&g_cursor[j], 1);
            g_inList[pos] = g_eh[e];
        }
    }
    __syncthreads();

    // (c) init: deg-0 -> head; others -> worklist
    for (int i = tid; i < NN; i += 1024) {
        int st = s_off[i];
        int en = (i < NN - 1) ? (int)s_off[i + 1] : total;
        if (st == en) {
            s_sc[i] = (short)i;
        } else {
            s_sc[i] = -1;
            int p = atomicAdd(&s_cnt, 1);
            g_actA[p] = i;
        }
    }
    __syncthreads();
    int nact = s_cnt;
    int* cur = g_actA;
    int* nxt = g_actB;

    for (int round = 0; round < 2048 && nact > 0; round++) {
        if (tid == 0) s_cnt = 0;
        __syncthreads();
        for (int t = tid; t < nact; t += 1024) {
            int i = cur[t];
            int st = s_off[i];
            int en = (i < NN - 1) ? (int)s_off[i + 1] : total;
            int m = 0x7fffffff, u = 0x7fffffff;
            for (int p = st; p < en; p++) {
                int h = g_inList[p];
                int c = s_sc[h];
                if (c == h)      m = min(m, h);
                else if (c < 0)  u = min(u, h);
            }
            if (m < u)                 s_sc[i] = (short)m;
            else if (u == 0x7fffffff)  s_sc[i] = (short)i;
            else { int p = atomicAdd(&s_cnt, 1); nxt[p] = i; }
        }
        __syncthreads();
        nact = s_cnt;
        int* tmp = cur; cur = nxt; nxt = tmp;
        __syncthreads();
    }

    // (d) stats
    for (int j = tid; j < NN; j += 1024) {
        int c = s_sc[j];
        atomicAdd(&g_count[c], 1);
        atomicAdd(&g_sum[c], g_s[j]);
        atomicMax(&g_maxY2[c], __float_as_uint(g_by2[j]));  // y2>=0 monotone
    }
    __syncthreads();

    // (e) first pick
    for (int j = tid; j < NN; j += 1024) {
        int c = s_sc[j];
        if (g_by2[j] >= __uint_as_float(g_maxY2[c])) atomicMin(&g_first[c], j);
    }
    __syncthreads();

    // (f) output: out[0..5N) = (N,5) rows, out[5N..6N) = keep as 0/1 floats.
    //     valid: counts >= nm/3  <=>  3*count >= nm (exact in ints)
    int nm = nmp[0];
    if (nm < 1 || nm > 1000000) {
        float f = __int_as_float(nm);
        nm = (int)f;
        if (nm < 1) nm = 1;
    }
    for (int j = tid; j < NN; j += 1024) {
        int c = s_sc[j];
        bool keep = (j == g_first[c]) && (3 * g_count[c] >= nm);
        float r0 = 0.f, r1 = 0.f, r2 = 0.f, r3 = 0.f, r4 = 0.f, kf = 0.f;
        if (keep) {
            r0 = g_bx1[j]; r1 = g_by1[j]; r2 = g_bx2[j]; r3 = g_by2[j];
            r4 = __fdiv_rn(g_sum[c], (float)nm);
            kf = 1.0f;
        }
        long long obase = (long long)j * 5;
        if (obase + 4 < out_size) {
            out[obase + 0] = r0; out[obase + 1] = r1; out[obase + 2] = r2;
            out[obase + 3] = r3; out[obase + 4] = r4;
        }
        long long kpos = (long long)NN * 5 + j;
        if (kpos < out_size) out[kpos] = kf;
    }
}

// ---------------------------------------------------------------------------
extern "C" void kernel_launch(void* const* d_in, const int* in_sizes, int n_in,
                              void* d_out, int out_size) {
    const float* boxes  = nullptr;
    const float* scores = nullptr;
    const int*   nmp    = nullptr;
    for (int k = 0; k < n_in; k++) {
        if (in_sizes[k] == NN * 4)      boxes  = (const float*)d_in[k];
        else if (in_sizes[k] == NN)     scores = (const float*)d_in[k];
        else if (in_sizes[k] == 1)      nmp    = (const int*)d_in[k];
    }
    if (!boxes)  boxes  = (const float*)d_in[0];
    if (!scores) scores = (const float*)d_in[1];
    if (!nmp)    nmp    = (const int*)d_in[n_in - 1];

    float* out = (float*)d_out;

    k_init<<<NN / 256, 256>>>(scores, boxes);
    k_rank<<<dim3(33, 4), 256>>>();        // x==32,y==0 = bin scan block
    k_gather<<<NN / 256, 256>>>(boxes, scores);
    k_edges<<<NN / 8, 256>>>();            // 8192 warps, warp per x-row
    k_post<<<1, 1024>>>(nmp, out, out_size);
}